// round 15
// baseline (speedup 1.0000x reference)
#include <cuda_runtime.h>
#include <cuda_fp16.h>
#include <cstdint>

#define H    8
#define Bn   32768
#define OF   32
#define NKS  36            // ksteps of 16 -> K = 576
#define MT   256           // samples per CTA
#define NT   128           // 4 warps, 64 samples/warp (4 m16 tiles)

// W fragments (single fp16 plane), packed for LDG.128:
// uint4 idx = ((h*NKS+ks)*2+ntp)*32+lane
__device__ uint4 g_wf4[H * NKS * 2 * 32];

// smem per warp: csh[ch*65+s] duplicated half2 (2080 u32) + xsw[i*65+s] fp32 (1040 f)
#define SSTR  65
#define WBLK  (32 * SSTR + 16 * SSTR)          // 3120 u32 words per warp
#define SM_TOTAL (4 * WBLK * 4)                // 49920 bytes

static __device__ __forceinline__ uint32_t cvt2(float p0, float p1) {
    __half2 hv = __floats2half2_rn(p0, p1);
    return *reinterpret_cast<uint32_t*>(&hv);
}
static __device__ __forceinline__ uint32_t hmul2u(uint32_t a, uint32_t b) {
    __half2 r = __hmul2(*reinterpret_cast<__half2*>(&a), *reinterpret_cast<__half2*>(&b));
    return *reinterpret_cast<uint32_t*>(&r);
}
static __device__ __forceinline__ uint32_t lows2(uint32_t a, uint32_t b) {
    __half2 r = __lows2half2(*reinterpret_cast<__half2*>(&a), *reinterpret_cast<__half2*>(&b));
    return *reinterpret_cast<uint32_t*>(&r);
}
static __device__ __forceinline__ void mma_f16(float d[4], const uint32_t a[4],
                                               uint32_t b0, uint32_t b1) {
    asm volatile(
        "mma.sync.aligned.m16n8k16.row.col.f32.f16.f16.f32 "
        "{%0,%1,%2,%3}, {%4,%5,%6,%7}, {%8,%9}, {%0,%1,%2,%3};"
        : "+f"(d[0]), "+f"(d[1]), "+f"(d[2]), "+f"(d[3])
        : "r"(a[0]), "r"(a[1]), "r"(a[2]), "r"(a[3]), "r"(b0), "r"(b1));
}

// permuted W': kp<512: W[o*17+(kp&15)][ch=kp>>4]; 512+i: bias(i); 528+q: W[o*17+16][q];
//              560: bias(16); else 0
static __device__ __forceinline__ float wval(const float* cw, const float* cb,
                                             int h, int kp, int o) {
    if (kp < 512) { int ch = kp >> 4, i = kp & 15; return cw[(h * 544 + o * 17 + i) * 32 + ch]; }
    if (kp < 528) return cb[h * 544 + o * 17 + (kp - 512)];
    if (kp < 560) return cw[(h * 544 + o * 17 + 16) * 32 + (kp - 528)];
    if (kp == 560) return cb[h * 544 + o * 17 + 16];
    return 0.0f;
}
__global__ void mml_prep_k(const float* __restrict__ cw, const float* __restrict__ cb) {
    int idx = blockIdx.x * blockDim.x + threadIdx.x;
    if (idx >= H * NKS * 2 * 32) return;
    int lane = idx & 31;
    int ntp  = (idx >> 5) & 1;
    int ks   = (idx >> 6) % NKS;
    int h    = (idx >> 6) / NKS;
    int g = lane >> 2, t = lane & 3;
    uint32_t v[4];
#pragma unroll
    for (int p = 0; p < 2; p++) {
        int o = (ntp * 2 + p) * 8 + g;
#pragma unroll
        for (int j = 0; j < 2; j++) {
            int k0 = ks * 16 + 2 * t + 8 * j;
            v[p * 2 + j] = cvt2(wval(cw, cb, h, k0, o), wval(cw, cb, h, k0 + 1, o));
        }
    }
    g_wf4[idx] = make_uint4(v[0], v[1], v[2], v[3]);
}

__global__ void __launch_bounds__(NT, 4)
mml_k(const float* __restrict__ input, const float* __restrict__ cond,
      float* __restrict__ out) {
    extern __shared__ uint32_t smu[];
    const int tid = threadIdx.x;
    const int wid = tid >> 5;
    const int lane = tid & 31;
    const int h = blockIdx.y;
    const size_t sbase = (size_t)(h * Bn + blockIdx.x * MT);
    const size_t wrow = sbase + wid * 64;      // this warp's first sample

    uint32_t* csh = smu + wid * WBLK;                    // (c,c) half2: [ch*65 + s]
    float* xsw = reinterpret_cast<float*>(csh + 32 * SSTR);  // fp32 x: [i*65 + s]

    // ---- warp-local staging (64 samples) ----
    {
        const float* cg = cond + wrow * 32;
#pragma unroll 1
        for (int s = 0; s < 64; s++) {
            float v = cg[s * 32 + lane];               // channel = lane
            csh[lane * SSTR + s] = cvt2(v, v);
        }
#pragma unroll
        for (int half = 0; half < 2; half++) {
            int s = half * 32 + lane;
            const float4* xg = reinterpret_cast<const float4*>(input + (wrow + s) * 16);
#pragma unroll
            for (int q = 0; q < 4; q++) {
                float4 v = xg[q];
                xsw[(q * 4 + 0) * SSTR + s] = v.x;
                xsw[(q * 4 + 1) * SSTR + s] = v.y;
                xsw[(q * 4 + 2) * SSTR + s] = v.z;
                xsw[(q * 4 + 3) * SSTR + s] = v.w;
            }
        }
    }
    __syncwarp();

    // per-lane x as half2 pairs, A-fragment layout, 8 rows: g+8r (r=0..7)
    const int g = lane >> 2, t = lane & 3;
    uint32_t xh[8][2];
#pragma unroll
    for (int r = 0; r < 8; r++) {
        int s = r * 8 + g;
        xh[r][0] = cvt2(xsw[(2 * t) * SSTR + s],     xsw[(2 * t + 1) * SSTR + s]);
        xh[r][1] = cvt2(xsw[(2 * t + 8) * SSTR + s], xsw[(2 * t + 9) * SSTR + s]);
    }

    float d[16][4];
#pragma unroll
    for (int n = 0; n < 16; n++)
#pragma unroll
        for (int e = 0; e < 4; e++) d[n][e] = 0.0f;

    const uint4* wH = g_wf4 + (size_t)h * NKS * 2 * 32 + lane;

    // issue all 32 HMMAs of one kstep from 4 A-tile fragment pairs a[4][4]
    auto do_mmas = [&](const uint32_t a[4][4], uint4 wa, uint4 wb) {
#pragma unroll
        for (int tt = 0; tt < 4; tt++) {
            mma_f16(d[tt * 4 + 0], a[tt], wa.x, wa.y);
            mma_f16(d[tt * 4 + 1], a[tt], wa.z, wa.w);
            mma_f16(d[tt * 4 + 2], a[tt], wb.x, wb.y);
            mma_f16(d[tt * 4 + 3], a[tt], wb.z, wb.w);
        }
    };

    // W prefetch state
    uint4 wA = wH[0];
    uint4 wB = wH[32];

    // ---- ksteps 0..31: P = cond[ks] * x[i] ----
#pragma unroll 1
    for (int c = 0; c < 8; c++) {
#pragma unroll
        for (int u = 0; u < 4; u++) {
            const int ks = c * 4 + u;
            uint4 nwA = wH[(ks + 1) * 2 * 32];
            uint4 nwB = wH[(ks + 1) * 2 * 32 + 32];
            const uint32_t* cn = csh + ks * SSTR;
            uint32_t a[4][4];
#pragma unroll
            for (int tt = 0; tt < 4; tt++) {
                uint32_t cva = cn[g + tt * 16];
                uint32_t cvb = cn[g + tt * 16 + 8];
                a[tt][0] = hmul2u(cva, xh[tt * 2 + 0][0]);
                a[tt][1] = hmul2u(cvb, xh[tt * 2 + 1][0]);
                a[tt][2] = hmul2u(cva, xh[tt * 2 + 0][1]);
                a[tt][3] = hmul2u(cvb, xh[tt * 2 + 1][1]);
            }
            do_mmas(a, wA, wB);
            wA = nwA; wB = nwB;
        }
    }
    // ---- kstep 32: P = x[i] (cv = 1); W already in wA/wB ----
    {
        uint32_t a[4][4];
#pragma unroll
        for (int tt = 0; tt < 4; tt++) {
            a[tt][0] = xh[tt * 2 + 0][0];
            a[tt][1] = xh[tt * 2 + 1][0];
            a[tt][2] = xh[tt * 2 + 0][1];
            a[tt][3] = xh[tt * 2 + 1][1];
        }
        do_mmas(a, wA, wB);
    }
    // ---- ksteps 33,34: P = cond[qb + kcol] ----
#pragma unroll
    for (int u = 0; u < 2; u++) {
        const int ks = 33 + u;
        const int qb = u * 16;
        const int i0 = 2 * t, i1 = 2 * t + 1, i2 = 2 * t + 8, i3 = 2 * t + 9;
        uint4 wa = wH[ks * 2 * 32];
        uint4 wb = wH[ks * 2 * 32 + 32];
        uint32_t a[4][4];
#pragma unroll
        for (int tt = 0; tt < 4; tt++) {
            int r0 = tt * 16 + g, r1 = tt * 16 + g + 8;
            a[tt][0] = lows2(csh[(qb + i0) * SSTR + r0], csh[(qb + i1) * SSTR + r0]);
            a[tt][1] = lows2(csh[(qb + i0) * SSTR + r1], csh[(qb + i1) * SSTR + r1]);
            a[tt][2] = lows2(csh[(qb + i2) * SSTR + r0], csh[(qb + i3) * SSTR + r0]);
            a[tt][3] = lows2(csh[(qb + i2) * SSTR + r1], csh[(qb + i3) * SSTR + r1]);
        }
        do_mmas(a, wa, wb);
    }
    // ---- kstep 35: P[.,560] = 1.0, rest 0 ----
    {
        uint4 wa = wH[35 * 2 * 32];
        uint4 wb = wH[35 * 2 * 32 + 32];
        uint32_t one = (t == 0) ? 0x00003C00u : 0u;
        uint32_t a[4][4];
#pragma unroll
        for (int tt = 0; tt < 4; tt++) {
            a[tt][0] = one; a[tt][1] = one; a[tt][2] = 0u; a[tt][3] = 0u;
        }
        do_mmas(a, wa, wb);
    }

    // ---- epilogue: 16 tiles -> rows wid*64 + tt*16 + {g, g+8} ----
    {
        const int m0 = wid * 64;
        const int t4 = lane & 3;
#pragma unroll
        for (int tt = 0; tt < 4; tt++) {
#pragma unroll
            for (int nt = 0; nt < 4; nt++) {
                const float* dd = d[tt * 4 + nt];
                int col = nt * 8 + 2 * t4;
                size_t r0 = sbase + m0 + tt * 16 + g;
                *reinterpret_cast<float2*>(out + r0 * OF + col) = make_float2(dd[0], dd[1]);
                *reinterpret_cast<float2*>(out + (r0 + 8) * OF + col) = make_float2(dd[2], dd[3]);
            }
        }
    }
}

extern "C" void kernel_launch(void* const* d_in, const int* in_sizes, int n_in,
                              void* d_out, int out_size) {
    const float* input = (const float*)d_in[0];
    const float* cond  = (const float*)d_in[1];
    const float* cw    = (const float*)d_in[2];
    const float* cb    = (const float*)d_in[3];
    float* out = (float*)d_out;

    int prep = H * NKS * 2 * 32;   // 18432
    mml_prep_k<<<(prep + 255) / 256, 256>>>(cw, cb);

    cudaFuncSetAttribute(mml_k, cudaFuncAttributeMaxDynamicSharedMemorySize, SM_TOTAL);
    dim3 grid(Bn / MT, H);         // (128, 8)
    mml_k<<<grid, NT, SM_TOTAL>>>(input, cond, out);
}

// round 16
// speedup vs baseline: 1.6648x; 1.6648x over previous
#include <cuda_runtime.h>
#include <cuda_fp16.h>
#include <cstdint>

#define H    8
#define Bn   32768
#define OF   32
#define NKS  36            // ksteps of 16 -> K = 576
#define MT   128           // samples per CTA
#define NT   128           // 4 warps, 32 samples/warp (2 m16 tiles)

// W fragments (single fp16 plane), packed for LDG.128:
// uint4 idx = ((h*NKS+ks)*2+ntp)*32+lane
__device__ uint4 g_wf4[H * NKS * 2 * 32];

// smem per warp: csh[ch*33+s] duplicated half2 (1056 u32) + xsw[i*33+s] fp32 (528 f)
#define WBLK  1584                     // u32 words per warp
#define SM_TOTAL (4 * WBLK * 4)        // 25344 bytes

static __device__ __forceinline__ uint32_t cvt2(float p0, float p1) {
    __half2 hv = __floats2half2_rn(p0, p1);
    return *reinterpret_cast<uint32_t*>(&hv);
}
static __device__ __forceinline__ uint32_t hmul2u(uint32_t a, uint32_t b) {
    __half2 r = __hmul2(*reinterpret_cast<__half2*>(&a), *reinterpret_cast<__half2*>(&b));
    return *reinterpret_cast<uint32_t*>(&r);
}
static __device__ __forceinline__ uint32_t lows2(uint32_t a, uint32_t b) {
    __half2 r = __lows2half2(*reinterpret_cast<__half2*>(&a), *reinterpret_cast<__half2*>(&b));
    return *reinterpret_cast<uint32_t*>(&r);
}
static __device__ __forceinline__ void mma_f16(float d[4], const uint32_t a[4],
                                               uint32_t b0, uint32_t b1) {
    asm volatile(
        "mma.sync.aligned.m16n8k16.row.col.f32.f16.f16.f32 "
        "{%0,%1,%2,%3}, {%4,%5,%6,%7}, {%8,%9}, {%0,%1,%2,%3};"
        : "+f"(d[0]), "+f"(d[1]), "+f"(d[2]), "+f"(d[3])
        : "r"(a[0]), "r"(a[1]), "r"(a[2]), "r"(a[3]), "r"(b0), "r"(b1));
}

// permuted W': kp<512: W[o*17+(kp&15)][ch=kp>>4]; 512+i: bias(i); 528+q: W[o*17+16][q];
//              560: bias(16); else 0
static __device__ __forceinline__ float wval(const float* cw, const float* cb,
                                             int h, int kp, int o) {
    if (kp < 512) { int ch = kp >> 4, i = kp & 15; return cw[(h * 544 + o * 17 + i) * 32 + ch]; }
    if (kp < 528) return cb[h * 544 + o * 17 + (kp - 512)];
    if (kp < 560) return cw[(h * 544 + o * 17 + 16) * 32 + (kp - 528)];
    if (kp == 560) return cb[h * 544 + o * 17 + 16];
    return 0.0f;
}
__global__ void mml_prep_k(const float* __restrict__ cw, const float* __restrict__ cb) {
    int idx = blockIdx.x * blockDim.x + threadIdx.x;
    if (idx >= H * NKS * 2 * 32) return;
    int lane = idx & 31;
    int ntp  = (idx >> 5) & 1;
    int ks   = (idx >> 6) % NKS;
    int h    = (idx >> 6) / NKS;
    int g = lane >> 2, t = lane & 3;
    uint32_t v[4];
#pragma unroll
    for (int p = 0; p < 2; p++) {
        int o = (ntp * 2 + p) * 8 + g;
#pragma unroll
        for (int j = 0; j < 2; j++) {
            int k0 = ks * 16 + 2 * t + 8 * j;
            v[p * 2 + j] = cvt2(wval(cw, cb, h, k0, o), wval(cw, cb, h, k0 + 1, o));
        }
    }
    g_wf4[idx] = make_uint4(v[0], v[1], v[2], v[3]);
}

__global__ void __launch_bounds__(NT, 6)
mml_k(const float* __restrict__ input, const float* __restrict__ cond,
      float* __restrict__ out) {
    extern __shared__ uint32_t smu[];
    const int tid = threadIdx.x;
    const int wid = tid >> 5;
    const int lane = tid & 31;
    const int h = blockIdx.y;
    const size_t sbase = (size_t)(h * Bn + blockIdx.x * MT);
    const size_t wrow = sbase + wid * 32;      // this warp's first sample

    uint32_t* csh = smu + wid * WBLK;          // duplicated half2 (c,c): [ch*33 + s]
    float* xsw = reinterpret_cast<float*>(csh + 1056);   // fp32 x: [i*33 + s]

    // ---- warp-local staging ----
    {
        const float* cg = cond + wrow * 32;
#pragma unroll
        for (int s = 0; s < 32; s++) {
            float v = cg[s * 32 + lane];               // channel = lane
            csh[lane * 33 + s] = cvt2(v, v);
        }
        const float4* xg = reinterpret_cast<const float4*>(input + (wrow + lane) * 16);
#pragma unroll
        for (int q = 0; q < 4; q++) {
            float4 v = xg[q];
            xsw[(q * 4 + 0) * 33 + lane] = v.x;
            xsw[(q * 4 + 1) * 33 + lane] = v.y;
            xsw[(q * 4 + 2) * 33 + lane] = v.z;
            xsw[(q * 4 + 3) * 33 + lane] = v.w;
        }
    }
    __syncwarp();

    // per-lane x as half2 pairs, A-fragment layout
    const int g = lane >> 2, t = lane & 3;
    uint32_t xh[4][2];
#pragma unroll
    for (int r = 0; r < 4; r++) {
        int s = r * 8 + g;
        xh[r][0] = cvt2(xsw[(2 * t) * 33 + s],     xsw[(2 * t + 1) * 33 + s]);
        xh[r][1] = cvt2(xsw[(2 * t + 8) * 33 + s], xsw[(2 * t + 9) * 33 + s]);
    }

    float d[8][4];
#pragma unroll
    for (int n = 0; n < 8; n++)
#pragma unroll
        for (int e = 0; e < 4; e++) d[n][e] = 0.0f;

    const uint4* wH = g_wf4 + (size_t)h * NKS * 2 * 32 + lane;

    auto do_mmas = [&](const uint32_t a0[4], const uint32_t a1[4], uint4 wa, uint4 wb) {
        mma_f16(d[0], a0, wa.x, wa.y);
        mma_f16(d[1], a0, wa.z, wa.w);
        mma_f16(d[2], a0, wb.x, wb.y);
        mma_f16(d[3], a0, wb.z, wb.w);
        mma_f16(d[4], a1, wa.x, wa.y);
        mma_f16(d[5], a1, wa.z, wa.w);
        mma_f16(d[6], a1, wb.x, wb.y);
        mma_f16(d[7], a1, wb.z, wb.w);
    };

    // ---- W prefetch state (cv loads stay in-loop; 6 CTAs hide the LDS) ----
    uint4 wA = wH[0];
    uint4 wB = wH[32];

    // ---- ksteps 0..31: P = cond[ks] * x[i] ----
#pragma unroll 1
    for (int c = 0; c < 8; c++) {
#pragma unroll
        for (int u = 0; u < 4; u++) {
            const int ks = c * 4 + u;
            uint4 nwA = wH[(ks + 1) * 2 * 32];
            uint4 nwB = wH[(ks + 1) * 2 * 32 + 32];
            const uint32_t* cn = csh + ks * 33;
            uint32_t cv0 = cn[g];
            uint32_t cv1 = cn[g + 8];
            uint32_t cv2 = cn[g + 16];
            uint32_t cv3 = cn[g + 24];
            uint32_t a0[4], a1[4];
            a0[0] = hmul2u(cv0, xh[0][0]);
            a0[1] = hmul2u(cv1, xh[1][0]);
            a0[2] = hmul2u(cv0, xh[0][1]);
            a0[3] = hmul2u(cv1, xh[1][1]);
            a1[0] = hmul2u(cv2, xh[2][0]);
            a1[1] = hmul2u(cv3, xh[3][0]);
            a1[2] = hmul2u(cv2, xh[2][1]);
            a1[3] = hmul2u(cv3, xh[3][1]);
            do_mmas(a0, a1, wA, wB);
            wA = nwA; wB = nwB;
        }
    }
    // ---- kstep 32: P = x[i] (cv = 1); W already prefetched in wA/wB ----
    {
        uint32_t a0[4] = { xh[0][0], xh[1][0], xh[0][1], xh[1][1] };
        uint32_t a1[4] = { xh[2][0], xh[3][0], xh[2][1], xh[3][1] };
        do_mmas(a0, a1, wA, wB);
    }
    // ---- ksteps 33,34: P = cond[qb + kcol] ----
#pragma unroll
    for (int u = 0; u < 2; u++) {
        const int ks = 33 + u;
        const int qb = u * 16;
        const int i0 = 2 * t, i1 = 2 * t + 1, i2 = 2 * t + 8, i3 = 2 * t + 9;
        uint4 wa = wH[ks * 2 * 32];
        uint4 wb = wH[ks * 2 * 32 + 32];
        uint32_t a0[4], a1[4];
        a0[0] = lows2(csh[(qb + i0) * 33 + g],      csh[(qb + i1) * 33 + g]);
        a0[1] = lows2(csh[(qb + i0) * 33 + g + 8],  csh[(qb + i1) * 33 + g + 8]);
        a0[2] = lows2(csh[(qb + i2) * 33 + g],      csh[(qb + i3) * 33 + g]);
        a0[3] = lows2(csh[(qb + i2) * 33 + g + 8],  csh[(qb + i3) * 33 + g + 8]);
        a1[0] = lows2(csh[(qb + i0) * 33 + g + 16], csh[(qb + i1) * 33 + g + 16]);
        a1[1] = lows2(csh[(qb + i0) * 33 + g + 24], csh[(qb + i1) * 33 + g + 24]);
        a1[2] = lows2(csh[(qb + i2) * 33 + g + 16], csh[(qb + i3) * 33 + g + 16]);
        a1[3] = lows2(csh[(qb + i2) * 33 + g + 24], csh[(qb + i3) * 33 + g + 24]);
        do_mmas(a0, a1, wa, wb);
    }
    // ---- kstep 35: P[.,560] = 1.0, rest 0 ----
    {
        uint4 wa = wH[35 * 2 * 32];
        uint4 wb = wH[35 * 2 * 32 + 32];
        uint32_t one = (t == 0) ? 0x00003C00u : 0u;
        uint32_t a0[4] = { one, one, 0u, 0u };
        uint32_t a1[4] = { one, one, 0u, 0u };
        do_mmas(a0, a1, wa, wb);
    }

    // ---- epilogue: 8 fragment tiles -> rows m0+{g,g+8,g+16,g+24} ----
    {
        const int m0 = wid * 32;
        const int t4 = lane & 3;
#pragma unroll
        for (int tt = 0; tt < 2; tt++) {
#pragma unroll
            for (int nt = 0; nt < 4; nt++) {
                const float* dd = d[tt * 4 + nt];
                int col = nt * 8 + 2 * t4;
                size_t r0 = sbase + m0 + tt * 16 + g;
                *reinterpret_cast<float2*>(out + r0 * OF + col) = make_float2(dd[0], dd[1]);
                *reinterpret_cast<float2*>(out + (r0 + 8) * OF + col) = make_float2(dd[2], dd[3]);
            }
        }
    }
}

extern "C" void kernel_launch(void* const* d_in, const int* in_sizes, int n_in,
                              void* d_out, int out_size) {
    const float* input = (const float*)d_in[0];
    const float* cond  = (const float*)d_in[1];
    const float* cw    = (const float*)d_in[2];
    const float* cb    = (const float*)d_in[3];
    float* out = (float*)d_out;

    int prep = H * NKS * 2 * 32;   // 18432
    mml_prep_k<<<(prep + 255) / 256, 256>>>(cw, cb);

    cudaFuncSetAttribute(mml_k, cudaFuncAttributeMaxDynamicSharedMemorySize, SM_TOTAL);
    dim3 grid(Bn / MT, H);         // (256, 8)
    mml_k<<<grid, NT, SM_TOTAL>>>(input, cond, out);
}